// round 1
// baseline (speedup 1.0000x reference)
#include <cuda_runtime.h>
#include <cstdint>

#define BB 8
#define CC 96
#define HH 256
#define WW 256
#define KK 7

// Effective per-channel weights for integer offsets dr = k - 6, k in [0,12)
__device__ float g_cwh[CC][12];
__device__ float g_cww[CC][12];
__device__ int   g_fast;
__device__ float g_rv;

__global__ void precompute_kernel(const float* __restrict__ wh,
                                  const float* __restrict__ ww,
                                  const float* __restrict__ rp) {
    int c = threadIdx.x;
    float rv = rp[0];
    if (rv < 1.0f) rv = 1.0f;
    if (c == 0) {
        g_rv = rv;
        float lo = floorf(-3.0f * rv);
        float hi = floorf(3.0f * rv) + 1.0f;
        g_fast = (lo >= -6.0f && hi <= 5.0f) ? 1 : 0;
    }
    if (c >= CC) return;
    float ah[12], aw[12];
    #pragma unroll
    for (int k = 0; k < 12; k++) { ah[k] = 0.f; aw[k] = 0.f; }
    #pragma unroll
    for (int i = 0; i < KK; i++) {
        float off = (float)(i - 3);
        float ofr = off * rv;
        float fl  = floorf(ofr);
        int   d   = (int)fl;
        float fr  = ofr - fl;
        int k0 = d + 6;
        float whv = wh[c * KK + i];
        float wwv = ww[c * KK + i];
        if (k0 >= 0 && k0 < 12)     { ah[k0]   += whv * (1.f - fr); aw[k0]   += wwv * (1.f - fr); }
        if (k0 + 1 >= 0 && k0 + 1 < 12) { ah[k0+1] += whv * fr;     aw[k0+1] += wwv * fr; }
    }
    #pragma unroll
    for (int k = 0; k < 12; k++) { g_cwh[c][k] = ah[k]; g_cww[c][k] = aw[k]; }
}

__device__ __forceinline__ void fma2(unsigned long long &d,
                                     unsigned long long a,
                                     unsigned long long b) {
    asm("fma.rn.f32x2 %0, %1, %2, %0;" : "+l"(d) : "l"(a), "l"(b));
}
__device__ __forceinline__ unsigned long long pk2(float lo, float hi) {
    return (unsigned long long)__float_as_uint(lo) |
           ((unsigned long long)__float_as_uint(hi) << 32);
}
__device__ __forceinline__ void upk2(unsigned long long v, float &lo, float &hi) {
    lo = __uint_as_float((unsigned int)(v & 0xffffffffull));
    hi = __uint_as_float((unsigned int)(v >> 32));
}

// Fast path: r in [1, 5/3)  => all effective taps fit in dr in [-6, 5]
// blockDim = (64, 2); each thread: 4 consecutive cols (float4), 32-row sweep.
__global__ __launch_bounds__(128) void fast_kernel(const float* __restrict__ x,
                                                   float* __restrict__ out) {
    if (!g_fast) return;
    int c  = blockIdx.z % CC;
    int tx = threadIdx.x;                                 // 0..63
    int strip = blockIdx.y * blockDim.y + threadIdx.y;    // 0..7
    int x4 = tx * 4;
    int y0 = strip * 32;                                  // multiple of 16
    const float* xc = x   + (size_t)blockIdx.z * (HH * WW);
    float*       oc = out + (size_t)blockIdx.z * (HH * WW);

    unsigned long long cwh2[12];
    float cww[12];
    #pragma unroll
    for (int k = 0; k < 12; k++) {
        float w = g_cwh[c][k];
        cwh2[k] = pk2(w, w);
        cww[k]  = g_cww[c][k];
    }

    // Register ring: 16 rows (as 2x u64 = one float4 each). slot(row) = row & 15.
    ulonglong2 ring[16];
    #pragma unroll
    for (int t = -6; t <= 5; t++) {
        int row = y0 + t;
        int slot = (t + 16) & 15;
        ulonglong2 v = make_ulonglong2(0ull, 0ull);
        if (row >= 0)  // row < HH always true in prologue (y0 <= 224)
            v = *reinterpret_cast<const ulonglong2*>(xc + (size_t)row * WW + x4);
        ring[slot] = v;
    }

    const bool pm2 = (tx >= 2), pm1 = (tx >= 1), pp1 = (tx <= 62), pp2 = (tx <= 61);
    const float4 z4 = make_float4(0.f, 0.f, 0.f, 0.f);

    #pragma unroll 1
    for (int half = 0; half < 2; half++) {
        int ybase = y0 + half * 16;
        #pragma unroll
        for (int u = 0; u < 16; u++) {
            int y = ybase + u;
            // Prefetch row y+6 (needed from next step onward) into slot (u+6)&15
            {
                int row = y + 6;
                ulonglong2 v = make_ulonglong2(0ull, 0ull);
                if (row < HH)
                    v = *reinterpret_cast<const ulonglong2*>(xc + (size_t)row * WW + x4);
                ring[(u + 6) & 15] = v;
            }
            // W-window loads for row y (center float4 comes from the ring)
            const float* rowp = xc + (size_t)y * WW;
            float4 wm2 = pm2 ? *reinterpret_cast<const float4*>(rowp + x4 - 8) : z4;
            float4 wm1 = pm1 ? *reinterpret_cast<const float4*>(rowp + x4 - 4) : z4;
            float4 wp1 = pp1 ? *reinterpret_cast<const float4*>(rowp + x4 + 4) : z4;
            float4 wp2 = pp2 ? *reinterpret_cast<const float4*>(rowp + x4 + 8) : z4;

            ulonglong2 ctr = ring[u & 15];   // row y
            float c0, c1, c2, c3;
            upk2(ctr.x, c0, c1);
            upk2(ctr.y, c2, c3);

            // identity term + H conv (packed f32x2 FMAs)
            unsigned long long acc01 = ctr.x;
            unsigned long long acc23 = ctr.y;
            #pragma unroll
            for (int k = 0; k < 12; k++) {           // dr = k - 6, row y+dr
                ulonglong2 rv = ring[(u + k + 10) & 15];
                fma2(acc01, cwh2[k], rv.x);
                fma2(acc23, cwh2[k], rv.y);
            }
            float a0, a1, a2, a3;
            upk2(acc01, a0, a1);
            upk2(acc23, a2, a3);

            // W conv: win[m] = col (x4 - 8 + m)
            float win[20];
            win[0]=wm2.x;  win[1]=wm2.y;  win[2]=wm2.z;  win[3]=wm2.w;
            win[4]=wm1.x;  win[5]=wm1.y;  win[6]=wm1.z;  win[7]=wm1.w;
            win[8]=c0;     win[9]=c1;     win[10]=c2;    win[11]=c3;
            win[12]=wp1.x; win[13]=wp1.y; win[14]=wp1.z; win[15]=wp1.w;
            win[16]=wp2.x; win[17]=wp2.y; win[18]=wp2.z; win[19]=wp2.w;
            #pragma unroll
            for (int k = 0; k < 12; k++) {           // dc = k - 6
                float w = cww[k];
                a0 += w * win[k + 2];
                a1 += w * win[k + 3];
                a2 += w * win[k + 4];
                a3 += w * win[k + 5];
            }

            *reinterpret_cast<float4*>(oc + (size_t)y * WW + x4) =
                make_float4(a0, a1, a2, a3);
        }
    }
}

// Generic fallback for r >= 5/3 (early-exits otherwise). One block per image,
// threads = columns, loop over rows.
__global__ void generic_kernel(const float* __restrict__ x,
                               const float* __restrict__ wh,
                               const float* __restrict__ ww,
                               float* __restrict__ out) {
    if (g_fast) return;
    float rv = g_rv;
    int xw = threadIdx.x;        // 0..255
    int zc = blockIdx.x;
    int c  = zc % CC;
    const float* xc = x + (size_t)zc * HH * WW;
    float*       oc = out + (size_t)zc * HH * WW;
    for (int y = 0; y < HH; y++) {
        float acc = xc[y * WW + xw];
        #pragma unroll
        for (int i = 0; i < KK; i++) {
            float ofr = (float)(i - 3) * rv;
            float fl  = floorf(ofr);
            int   d   = (int)fl;
            float fr  = ofr - fl;
            int r0 = y + d, r1 = r0 + 1;
            float s0 = (r0 >= 0 && r0 < HH) ? xc[r0 * WW + xw] : 0.f;
            float s1 = (r1 >= 0 && r1 < HH) ? xc[r1 * WW + xw] : 0.f;
            acc += wh[c * KK + i] * (s0 * (1.f - fr) + s1 * fr);
            int c0i = xw + d, c1i = c0i + 1;
            float t0 = (c0i >= 0 && c0i < WW) ? xc[y * WW + c0i] : 0.f;
            float t1 = (c1i >= 0 && c1i < WW) ? xc[y * WW + c1i] : 0.f;
            acc += ww[c * KK + i] * (t0 * (1.f - fr) + t1 * fr);
        }
        oc[y * WW + xw] = acc;
    }
}

extern "C" void kernel_launch(void* const* d_in, const int* in_sizes, int n_in,
                              void* d_out, int out_size) {
    const float* x  = (const float*)d_in[0];
    const float* wh = (const float*)d_in[1];
    const float* ww = (const float*)d_in[2];
    const float* r  = (const float*)d_in[3];
    float* out = (float*)d_out;

    int nimg = in_sizes[0] / (HH * WW);   // B*C = 768

    precompute_kernel<<<1, 128>>>(wh, ww, r);

    dim3 blk(64, 2, 1);
    dim3 grd(1, 4, nimg);
    fast_kernel<<<grd, blk>>>(x, out);

    generic_kernel<<<nimg, WW>>>(x, wh, ww, out);
}

// round 2
// speedup vs baseline: 1.1025x; 1.1025x over previous
#include <cuda_runtime.h>
#include <cstdint>

#define CC 96
#define HH 256
#define WW 256
#define KK 7

__device__ __forceinline__ void fma2(unsigned long long &d,
                                     unsigned long long a,
                                     unsigned long long b) {
    asm("fma.rn.f32x2 %0, %1, %2, %0;" : "+l"(d) : "l"(a), "l"(b));
}
__device__ __forceinline__ unsigned long long pk2(float lo, float hi) {
    return (unsigned long long)__float_as_uint(lo) |
           ((unsigned long long)__float_as_uint(hi) << 32);
}
__device__ __forceinline__ void upk2(unsigned long long v, float &lo, float &hi) {
    lo = __uint_as_float((unsigned int)(v & 0xffffffffull));
    hi = __uint_as_float((unsigned int)(v >> 32));
}

// One fused kernel. blockDim=(64,2), grid=(1,2,nimg).
// Each thread: 4 consecutive cols (float4), sweeping a 64-row strip.
// Fast path (r < 5/3): folded 12-tap integer-offset conv, 16-slot register ring.
// Generic path (r >= 5/3): direct 7-tap bilinear gather (same pixel mapping).
__global__ __launch_bounds__(128) void caxial_kernel(const float* __restrict__ x,
                                                     const float* __restrict__ wh,
                                                     const float* __restrict__ ww,
                                                     const float* __restrict__ rp,
                                                     float* __restrict__ out) {
    const int c  = blockIdx.z % CC;
    const int tx = threadIdx.x;                               // 0..63
    const int strip = blockIdx.y * 2 + threadIdx.y;           // 0..3
    const int x4 = tx * 4;
    const int y0 = strip * 64;                                // multiple of 16
    const float* xc = x   + (size_t)blockIdx.z * (HH * WW);
    float*       oc = out + (size_t)blockIdx.z * (HH * WW);

    float rv = rp[0];
    if (rv < 1.0f) rv = 1.0f;

    // Per-tap raw data (7 taps)
    float whv[KK], wwv[KK], fri[KK];
    int   k0i[KK];
    #pragma unroll
    for (int i = 0; i < KK; i++) {
        float ofr = (float)(i - 3) * rv;
        float fl  = floorf(ofr);
        k0i[i] = (int)fl + 6;
        fri[i] = ofr - fl;
        whv[i] = wh[c * KK + i];
        wwv[i] = ww[c * KK + i];
    }

    const bool fast = (k0i[0] >= 0) && (k0i[KK - 1] + 1 <= 11);

    if (fast) {
        // Fold 7 bilinear taps into 12 integer-offset weights (dr = k - 6)
        unsigned long long cwh2[12];
        float cww[12];
        #pragma unroll
        for (int k = 0; k < 12; k++) {
            float sh = 0.f, sw = 0.f;
            #pragma unroll
            for (int i = 0; i < KK; i++) {
                if (k0i[i] == k)     { sh += whv[i] * (1.f - fri[i]); sw += wwv[i] * (1.f - fri[i]); }
                if (k0i[i] + 1 == k) { sh += whv[i] * fri[i];         sw += wwv[i] * fri[i]; }
            }
            cwh2[k] = pk2(sh, sh);
            cww[k]  = sw;
        }

        // Register ring: 16 rows, one float4 each (as 2x u64). slot(row) = row & 15.
        ulonglong2 ring[16];
        #pragma unroll
        for (int t = -6; t <= 5; t++) {
            int row = y0 + t;
            ulonglong2 v = make_ulonglong2(0ull, 0ull);
            if (row >= 0)   // row < HH always true in prologue (y0 <= 192)
                v = *reinterpret_cast<const ulonglong2*>(xc + (size_t)row * WW + x4);
            ring[(t + 16) & 15] = v;
        }

        const bool pm2 = (tx >= 2), pm1 = (tx >= 1), pp1 = (tx <= 62), pp2 = (tx <= 61);
        const float4 z4 = make_float4(0.f, 0.f, 0.f, 0.f);

        #pragma unroll 1
        for (int half = 0; half < 4; half++) {
            int ybase = y0 + half * 16;
            #pragma unroll
            for (int u = 0; u < 16; u++) {
                int y = ybase + u;
                // Prefetch row y+6 into slot (u+6)&15 (used starting next step)
                {
                    int row = y + 6;
                    ulonglong2 v = make_ulonglong2(0ull, 0ull);
                    if (row < HH)
                        v = *reinterpret_cast<const ulonglong2*>(xc + (size_t)row * WW + x4);
                    ring[(u + 6) & 15] = v;
                }
                // W-window side loads (center comes from the ring)
                const float* rowp = xc + (size_t)y * WW;
                float4 wm2 = pm2 ? *reinterpret_cast<const float4*>(rowp + x4 - 8) : z4;
                float4 wm1 = pm1 ? *reinterpret_cast<const float4*>(rowp + x4 - 4) : z4;
                float4 wp1 = pp1 ? *reinterpret_cast<const float4*>(rowp + x4 + 4) : z4;
                float4 wp2 = pp2 ? *reinterpret_cast<const float4*>(rowp + x4 + 8) : z4;

                ulonglong2 ctr = ring[u & 15];       // row y
                float c0, c1, c2, c3;
                upk2(ctr.x, c0, c1);
                upk2(ctr.y, c2, c3);

                // identity + H conv (packed f32x2 FMAs)
                unsigned long long acc01 = ctr.x;
                unsigned long long acc23 = ctr.y;
                #pragma unroll
                for (int k = 0; k < 12; k++) {       // row y + (k-6)
                    ulonglong2 rv2 = ring[(u + k + 10) & 15];
                    fma2(acc01, cwh2[k], rv2.x);
                    fma2(acc23, cwh2[k], rv2.y);
                }
                float a0, a1, a2, a3;
                upk2(acc01, a0, a1);
                upk2(acc23, a2, a3);

                // W conv: win[m] = col (x4 - 8 + m)
                float win[20];
                win[0]=wm2.x;  win[1]=wm2.y;  win[2]=wm2.z;  win[3]=wm2.w;
                win[4]=wm1.x;  win[5]=wm1.y;  win[6]=wm1.z;  win[7]=wm1.w;
                win[8]=c0;     win[9]=c1;     win[10]=c2;    win[11]=c3;
                win[12]=wp1.x; win[13]=wp1.y; win[14]=wp1.z; win[15]=wp1.w;
                win[16]=wp2.x; win[17]=wp2.y; win[18]=wp2.z; win[19]=wp2.w;
                #pragma unroll
                for (int k = 0; k < 12; k++) {       // col x + (k-6)
                    float w = cww[k];
                    a0 += w * win[k + 2];
                    a1 += w * win[k + 3];
                    a2 += w * win[k + 4];
                    a3 += w * win[k + 5];
                }

                __stcs(reinterpret_cast<float4*>(oc + (size_t)y * WW + x4),
                       make_float4(a0, a1, a2, a3));
            }
        }
    } else {
        // Generic path: direct 7-tap bilinear gather along both axes.
        #pragma unroll 1
        for (int yy = 0; yy < 64; yy++) {
            int y = y0 + yy;
            float acc[4];
            #pragma unroll
            for (int j = 0; j < 4; j++) acc[j] = xc[(size_t)y * WW + x4 + j];
            #pragma unroll
            for (int i = 0; i < KK; i++) {
                int   d  = k0i[i] - 6;
                float fr = fri[i];
                int r0 = y + d, r1 = r0 + 1;
                #pragma unroll
                for (int j = 0; j < 4; j++) {
                    int col = x4 + j;
                    float s0 = (r0 >= 0 && r0 < HH) ? xc[(size_t)r0 * WW + col] : 0.f;
                    float s1 = (r1 >= 0 && r1 < HH) ? xc[(size_t)r1 * WW + col] : 0.f;
                    acc[j] += whv[i] * (s0 * (1.f - fr) + s1 * fr);
                    int c0i = col + d, c1i = c0i + 1;
                    float t0 = (c0i >= 0 && c0i < WW) ? xc[(size_t)y * WW + c0i] : 0.f;
                    float t1 = (c1i >= 0 && c1i < WW) ? xc[(size_t)y * WW + c1i] : 0.f;
                    acc[j] += wwv[i] * (t0 * (1.f - fr) + t1 * fr);
                }
            }
            #pragma unroll
            for (int j = 0; j < 4; j++) oc[(size_t)y * WW + x4 + j] = acc[j];
        }
    }
}

extern "C" void kernel_launch(void* const* d_in, const int* in_sizes, int n_in,
                              void* d_out, int out_size) {
    const float* x  = (const float*)d_in[0];
    const float* wh = (const float*)d_in[1];
    const float* ww = (const float*)d_in[2];
    const float* r  = (const float*)d_in[3];
    float* out = (float*)d_out;

    int nimg = in_sizes[0] / (HH * WW);   // B*C = 768

    dim3 blk(64, 2, 1);
    dim3 grd(1, 2, nimg);
    caxial_kernel<<<grd, blk>>>(x, wh, ww, r, out);
}